// round 14
// baseline (speedup 1.0000x reference)
#include <cuda_runtime.h>
#include <cuda_bf16.h>
#include <math.h>
#include <stdint.h>

// Problem dims
#define T_DIM 4096
#define B_DIM 8
#define C_DIM 1024
#define F_DIM 128
#define NPROJ 6
#define N6 (NPROJ * F_DIM)          // 768
#define M_DIM (T_DIM * B_DIM)       // 32768
#define G_GRP 64                    // row groups per batch for scan
#define R_ROWS (F_DIM / G_GRP)      // 2 rows per warp

#define INV_SQRT_F 0.08838834764831845f  // 1/sqrt(128)

// Scan SMEM pipeline
#define CHUNK 16                    // steps per chunk
#define SLOT_F 528                  // floats per step slot (4*128 + c + s + pad)
#define BUF_F (CHUNK * SLOT_F)      // floats per chunk buffer
#define SCAN_SMEM (2 * BUF_F * 4)   // bytes (67584)

// ---------------------------------------------------------------------------
// Scratch (static device arrays: allocation-free per harness rules)
// ---------------------------------------------------------------------------
__device__ float d_b6[N6];                                            // packed biases
__device__ float d_P[(size_t)M_DIM * N6];                             // 96 MB projections
__device__ float d_opart[(size_t)M_DIM * G_GRP * F_DIM];              // 1 GB partials
__device__ float d_stfb[(size_t)B_DIM * F_DIM * F_DIM];               // state fallback
__device__ __nv_bfloat16 d_xh[(size_t)M_DIM * C_DIM];                 // 64 MB x hi
__device__ __nv_bfloat16 d_xl[(size_t)M_DIM * C_DIM];                 // 64 MB x lo
__device__ __nv_bfloat16 d_W6h[(size_t)N6 * C_DIM];                   // 1.5 MB
__device__ __nv_bfloat16 d_W6l[(size_t)N6 * C_DIM];                   // 1.5 MB
__device__ __nv_bfloat16 d_Owh[(size_t)C_DIM * F_DIM];
__device__ __nv_bfloat16 d_Owl[(size_t)C_DIM * F_DIM];
__device__ __nv_bfloat16 d_oh[(size_t)M_DIM * F_DIM];                 // 8 MB
__device__ __nv_bfloat16 d_ol[(size_t)M_DIM * F_DIM];                 // 8 MB

// ---------------------------------------------------------------------------
// helpers
// ---------------------------------------------------------------------------
__device__ __forceinline__ void split1(float v, __nv_bfloat16& h, __nv_bfloat16& l) {
    h = __float2bfloat16_rn(v);
    l = __float2bfloat16_rn(v - __bfloat162float(h));
}

__device__ __forceinline__ void cp16(uint32_t dst, const void* src) {
    asm volatile("cp.async.ca.shared.global [%0], [%1], 16;"
                 :: "r"(dst), "l"(src));
}

__device__ __forceinline__ void cp8(uint32_t dst, const void* src) {
    asm volatile("cp.async.ca.shared.global [%0], [%1], 8;"
                 :: "r"(dst), "l"(src));
}

// dummy kernel: keeps the scan at ncu capture position 4
__global__ void noop_kernel() {}

// ---------------------------------------------------------------------------
// K0: pack biases + split weights AND x into bf16 hi/lo (merged kernel)
// ---------------------------------------------------------------------------
__global__ void pack_split_kernel(
    const float* __restrict__ xin,
    const float* __restrict__ Aw, const float* __restrict__ Bw,
    const float* __restrict__ Cw, const float* __restrict__ Dw,
    const float* __restrict__ Iw, const float* __restrict__ Sw,
    const float* __restrict__ Ab, const float* __restrict__ Bb,
    const float* __restrict__ Cb, const float* __restrict__ Db,
    const float* __restrict__ Ib, const float* __restrict__ Sb,
    const float* __restrict__ Ow)
{
    size_t i4 = (size_t)blockIdx.x * blockDim.x + threadIdx.x;
    const size_t total4 = (size_t)M_DIM * C_DIM / 4;
    if (i4 < total4) {
        float4 v = ((const float4*)xin)[i4];
        __nv_bfloat16 h0, l0, h1, l1, h2, l2, h3, l3;
        split1(v.x, h0, l0); split1(v.y, h1, l1);
        split1(v.z, h2, l2); split1(v.w, h3, l3);
        uint2 ph, pl;
        ph.x = (uint32_t)__bfloat16_as_ushort(h0) | ((uint32_t)__bfloat16_as_ushort(h1) << 16);
        ph.y = (uint32_t)__bfloat16_as_ushort(h2) | ((uint32_t)__bfloat16_as_ushort(h3) << 16);
        pl.x = (uint32_t)__bfloat16_as_ushort(l0) | ((uint32_t)__bfloat16_as_ushort(l1) << 16);
        pl.y = (uint32_t)__bfloat16_as_ushort(l2) | ((uint32_t)__bfloat16_as_ushort(l3) << 16);
        ((uint2*)d_xh)[i4] = ph;
        ((uint2*)d_xl)[i4] = pl;
    }
    const size_t per = (size_t)F_DIM * C_DIM;  // 131072
    if (i4 < per) {
        size_t i = i4;
        split1(Aw[i], d_W6h[0 * per + i], d_W6l[0 * per + i]);
        split1(Bw[i], d_W6h[1 * per + i], d_W6l[1 * per + i]);
        split1(Cw[i], d_W6h[2 * per + i], d_W6l[2 * per + i]);
        split1(Dw[i], d_W6h[3 * per + i], d_W6l[3 * per + i]);
        split1(Iw[i], d_W6h[4 * per + i], d_W6l[4 * per + i]);
        split1(Sw[i], d_W6h[5 * per + i], d_W6l[5 * per + i]);
        split1(Ow[i], d_Owh[i], d_Owl[i]);
    }
    if (i4 < F_DIM) {
        size_t i = i4;
        d_b6[0 * F_DIM + i] = Ab[i];
        d_b6[1 * F_DIM + i] = Bb[i];
        d_b6[2 * F_DIM + i] = Cb[i];
        d_b6[3 * F_DIM + i] = Db[i];
        d_b6[4 * F_DIM + i] = Ib[i];
        d_b6[5 * F_DIM + i] = Sb[i];
    }
}

// ---------------------------------------------------------------------------
// K1/K4: 3xBF16 GEMM, cp.async 2-stage pipeline + ldmatrix + mma.m16n8k16 (NT)
// Epilogue transform (K1 only, bias != null, N == N6): N-tile 1 (slot b)
// multiplies by 1/sqrt(F); N-tile 4 (slot i) applies sigmoid.
// ---------------------------------------------------------------------------
#define ASTRIDE 40
#define TILE_E (128 * ASTRIDE)
#define TILE_B (TILE_E * 2)
#define STAGE_B (4 * TILE_B)
#define GEMM_SMEM (2 * STAGE_B)

__device__ __forceinline__ void ldm_x4(uint32_t (&r)[4], const __nv_bfloat16* p) {
    uint32_t addr = (uint32_t)__cvta_generic_to_shared(p);
    asm volatile("ldmatrix.sync.aligned.m8n8.x4.shared.b16 {%0,%1,%2,%3}, [%4];"
                 : "=r"(r[0]), "=r"(r[1]), "=r"(r[2]), "=r"(r[3]) : "r"(addr));
}

__device__ __forceinline__ void mma_bf16(float* d, const uint32_t* a,
                                         uint32_t b0, uint32_t b1) {
    asm volatile(
        "mma.sync.aligned.m16n8k16.row.col.f32.bf16.bf16.f32 "
        "{%0,%1,%2,%3}, {%4,%5,%6,%7}, {%8,%9}, {%0,%1,%2,%3};"
        : "+f"(d[0]), "+f"(d[1]), "+f"(d[2]), "+f"(d[3])
        : "r"(a[0]), "r"(a[1]), "r"(a[2]), "r"(a[3]), "r"(b0), "r"(b1));
}

__device__ __forceinline__ float epi_op(float v, int mode) {
    if (mode == 1) return v * INV_SQRT_F;
    if (mode == 2) return 1.0f / (1.0f + __expf(-v));
    return v;
}

__global__ void __launch_bounds__(256, 2)
bf16_gemm_async(const __nv_bfloat16* __restrict__ Ah,
                const __nv_bfloat16* __restrict__ Al,
                const __nv_bfloat16* __restrict__ Bh,
                const __nv_bfloat16* __restrict__ Bl,
                const float* __restrict__ bias, float* __restrict__ C,
                int M, int N, int K)
{
    extern __shared__ __align__(16) __nv_bfloat16 smd[];

    const int tid = threadIdx.x;
    const int wid = tid >> 5;
    const int lane = tid & 31;
    const int grp = lane >> 2;
    const int tig = lane & 3;

    const int bm = blockIdx.y * 128;
    const int bn = blockIdx.x * 128;
    const int warp_m = (wid >> 1) * 32;
    const int warp_n = (wid & 1) * 64;

    float acc[2][8][4];
#pragma unroll
    for (int mt = 0; mt < 2; mt++)
#pragma unroll
        for (int nt = 0; nt < 8; nt++)
#pragma unroll
            for (int q = 0; q < 4; q++) acc[mt][nt][q] = 0.0f;

    const int lrow = tid >> 1;
    const int cb = (tid & 1) * 2;

    const __nv_bfloat16* gsrc[4];
    gsrc[0] = Ah + (size_t)(bm + lrow) * K;
    gsrc[1] = Al + (size_t)(bm + lrow) * K;
    gsrc[2] = Bh + (size_t)(bn + lrow) * K;
    gsrc[3] = Bl + (size_t)(bn + lrow) * K;

    const uint32_t smem_base = (uint32_t)__cvta_generic_to_shared(smd);
    const uint32_t dst0 = smem_base + (uint32_t)(lrow * ASTRIDE * 2 + cb * 16);

    const int a_e0 = (warp_m + (lane & 15)) * ASTRIDE + ((lane >> 4) & 1) * 8;
    const int b_e0 = (warp_n + (lane & 7) + ((lane >> 4) & 1) * 8) * ASTRIDE
                   + ((lane >> 3) & 1) * 8;

#define ISSUE_STAGE(stg, kk) do {                                          \
    uint32_t _d = dst0 + (uint32_t)(stg) * STAGE_B;                        \
    _Pragma("unroll")                                                      \
    for (int _m = 0; _m < 4; _m++) {                                       \
        cp16(_d + 0,  gsrc[_m] + (kk) + (cb + 0) * 8);                     \
        cp16(_d + 16, gsrc[_m] + (kk) + (cb + 1) * 8);                     \
        _d += TILE_B;                                                      \
    }                                                                      \
    asm volatile("cp.async.commit_group;");                                \
} while (0)

    const int niter = K >> 5;
    ISSUE_STAGE(0, 0);

    for (int i = 0; i < niter; i++) {
        if (i + 1 < niter) {
            ISSUE_STAGE((i + 1) & 1, (i + 1) * 32);
            asm volatile("cp.async.wait_group 1;");
        } else {
            asm volatile("cp.async.wait_group 0;");
        }
        __syncthreads();

        const __nv_bfloat16* sAh = smd + (size_t)((i & 1) * 4 + 0) * TILE_E;
        const __nv_bfloat16* sAl = smd + (size_t)((i & 1) * 4 + 1) * TILE_E;
        const __nv_bfloat16* sBh = smd + (size_t)((i & 1) * 4 + 2) * TILE_E;
        const __nv_bfloat16* sBl = smd + (size_t)((i & 1) * 4 + 3) * TILE_E;

#pragma unroll
        for (int ks = 0; ks < 2; ks++) {
            uint32_t afh[2][4], afl[2][4];
#pragma unroll
            for (int mt = 0; mt < 2; mt++) {
                int e = a_e0 + mt * 16 * ASTRIDE + ks * 16;
                ldm_x4(afh[mt], sAh + e);
                ldm_x4(afl[mt], sAl + e);
            }
#pragma unroll
            for (int ntp = 0; ntp < 4; ntp++) {
                uint32_t bh[4], bl[4];
                int e = b_e0 + ntp * 16 * ASTRIDE + ks * 16;
                ldm_x4(bh, sBh + e);
                ldm_x4(bl, sBl + e);
#pragma unroll
                for (int mt = 0; mt < 2; mt++) {
                    mma_bf16(acc[mt][2 * ntp],     afh[mt], bh[0], bh[1]);
                    mma_bf16(acc[mt][2 * ntp],     afh[mt], bl[0], bl[1]);
                    mma_bf16(acc[mt][2 * ntp],     afl[mt], bh[0], bh[1]);
                    mma_bf16(acc[mt][2 * ntp + 1], afh[mt], bh[2], bh[3]);
                    mma_bf16(acc[mt][2 * ntp + 1], afh[mt], bl[2], bl[3]);
                    mma_bf16(acc[mt][2 * ntp + 1], afl[mt], bh[2], bh[3]);
                }
            }
        }
        __syncthreads();
    }
#undef ISSUE_STAGE

    int mode = 0;
    if (bias != nullptr && N == N6) {
        if (bn == 1 * F_DIM) mode = 1;        // slot b: scale by 1/sqrt(F)
        else if (bn == 4 * F_DIM) mode = 2;   // slot i: sigmoid
    }

#pragma unroll
    for (int mt = 0; mt < 2; mt++) {
        int r0 = bm + warp_m + mt * 16 + grp;
#pragma unroll
        for (int nt = 0; nt < 8; nt++) {
            int col = bn + warp_n + nt * 8 + 2 * tig;
            float b0 = 0.f, b1 = 0.f;
            if (bias != nullptr) { b0 = bias[col]; b1 = bias[col + 1]; }
            float2 v0 = make_float2(epi_op(acc[mt][nt][0] + b0, mode),
                                    epi_op(acc[mt][nt][1] + b1, mode));
            float2 v1 = make_float2(epi_op(acc[mt][nt][2] + b0, mode),
                                    epi_op(acc[mt][nt][3] + b1, mode));
            *(float2*)(C + (size_t)r0 * N + col) = v0;
            *(float2*)(C + (size_t)(r0 + 8) * N + col) = v1;
        }
    }
}

// ---------------------------------------------------------------------------
// K2: sequential scan with SMEM chunk pipeline. G_GRP=64 -> 2 rows per warp.
// Grid (G_GRP, B_DIM), 32 threads per CTA. Lane l owns columns [4l, 4l+4).
// Slot b pre-scaled, slot i pre-sigmoided (GEMM epilogue).
// c/s copied with 8-byte cp.async (global offset 8g only 8B-aligned).
// 2-way warp reduction: 7 shfls (1 row-fold + 4 butterfly + 2 broadcasts).
// Slot layout (floats): a[0..127], b'[128..255], d[256..383], g[384..511],
//                       c[512..513], s[516..517], pad -> SLOT_F
// ---------------------------------------------------------------------------
__global__ void __launch_bounds__(32)
scan_kernel(const float* __restrict__ P, const float* __restrict__ state_in,
            float* __restrict__ opart, float* __restrict__ state_out)
{
    extern __shared__ __align__(16) float sm[];

    const int g = blockIdx.x;
    const int b = blockIdx.y;
    const int l = threadIdx.x;
    const int rowbase = g * R_ROWS;

    const uint32_t smb = (uint32_t)__cvta_generic_to_shared(sm);

#define ISSUE_CHUNK(cc, bi) do {                                              \
    const int _t0 = (cc) * CHUNK;                                             \
    _Pragma("unroll 4")                                                       \
    for (int _s = 0; _s < CHUNK; _s++) {                                      \
        const float* _src = P + (size_t)((size_t)(_t0 + _s) * B_DIM + b) * N6;\
        uint32_t _dst = smb + (uint32_t)(((bi) * BUF_F + _s * SLOT_F) * 4);   \
        cp16(_dst + (uint32_t)(l * 16),          _src + 0 * F_DIM + l * 4);   \
        cp16(_dst + (uint32_t)(512 + l * 16),    _src + 1 * F_DIM + l * 4);   \
        cp16(_dst + (uint32_t)(1024 + l * 16),   _src + 3 * F_DIM + l * 4);   \
        cp16(_dst + (uint32_t)(1536 + l * 16),   _src + 4 * F_DIM + l * 4);   \
        if (l == 0) cp8(_dst + 2048, _src + 2 * F_DIM + rowbase);             \
        if (l == 1) cp8(_dst + 2064, _src + 5 * F_DIM + rowbase);             \
    }                                                                         \
    asm volatile("cp.async.commit_group;");                                   \
} while (0)

    // initial state
    float4 st[R_ROWS];
    {
        const float* sb = state_in + ((size_t)b * F_DIM + rowbase) * F_DIM + 4 * l;
#pragma unroll
        for (int r = 0; r < R_ROWS; r++)
            st[r] = *(const float4*)(sb + r * F_DIM);
    }

    ISSUE_CHUNK(0, 0);
    ISSUE_CHUNK(1, 1);

    const bool hi16 = (l & 16) != 0;

    const int NCHUNK = T_DIM / CHUNK;   // 256
#pragma unroll 1
    for (int cc = 0; cc < NCHUNK; cc++) {
        asm volatile("cp.async.wait_group 1;");
        __syncwarp();

        const int bi = cc & 1;
        const float* buf = sm + (size_t)bi * BUF_F;

#pragma unroll 4
        for (int s = 0; s < CHUNK; s++) {
            const int t = cc * CHUNK + s;
            const float* sp = buf + s * SLOT_F;

            float4 a  = *(const float4*)(sp + 4 * l);
            float4 bb = *(const float4*)(sp + 128 + 4 * l);   // pre-scaled
            float4 dd = *(const float4*)(sp + 256 + 4 * l);
            float4 gg = *(const float4*)(sp + 384 + 4 * l);   // pre-sigmoided

            // per-lane partial dots (2 rows)
            float p0, p1;
            {
                float m01 = fmaf(st[0].y, a.y, st[0].x * a.x);
                float m23 = fmaf(st[0].w, a.w, st[0].z * a.z);
                p0 = m01 + m23;
                float n01 = fmaf(st[1].y, a.y, st[1].x * a.x);
                float n23 = fmaf(st[1].w, a.w, st[1].z * a.z);
                p1 = n01 + n23;
            }

            // 7-shfl 2-way allsum:
            float sA = hi16 ? p0 : p1;
            float rA = __shfl_xor_sync(0xffffffffu, sA, 16);
            float w = (hi16 ? p1 : p0) + rA;   // lo half: row0, hi half: row1
            w += __shfl_xor_sync(0xffffffffu, w, 8);
            w += __shfl_xor_sync(0xffffffffu, w, 4);
            w += __shfl_xor_sync(0xffffffffu, w, 2);
            w += __shfl_xor_sync(0xffffffffu, w, 1);
            float v0 = __shfl_sync(0xffffffffu, w, 0);
            float v1 = __shfl_sync(0xffffffffu, w, 16);

            const float c0 = sp[512];
            const float c1 = sp[513];
            const float s0 = sp[516];
            const float s1 = sp[517];

            // st = st*g + v*b' + c*d ; po = s0*st0 + s1*st1
            st[0].x = fmaf(st[0].x, gg.x, fmaf(v0, bb.x, c0 * dd.x));
            st[0].y = fmaf(st[0].y, gg.y, fmaf(v0, bb.y, c0 * dd.y));
            st[0].z = fmaf(st[0].z, gg.z, fmaf(v0, bb.z, c0 * dd.z));
            st[0].w = fmaf(st[0].w, gg.w, fmaf(v0, bb.w, c0 * dd.w));
            st[1].x = fmaf(st[1].x, gg.x, fmaf(v1, bb.x, c1 * dd.x));
            st[1].y = fmaf(st[1].y, gg.y, fmaf(v1, bb.y, c1 * dd.y));
            st[1].z = fmaf(st[1].z, gg.z, fmaf(v1, bb.z, c1 * dd.z));
            st[1].w = fmaf(st[1].w, gg.w, fmaf(v1, bb.w, c1 * dd.w));

            float4 po;
            po.x = fmaf(s1, st[1].x, s0 * st[0].x);
            po.y = fmaf(s1, st[1].y, s0 * st[0].y);
            po.z = fmaf(s1, st[1].z, s0 * st[0].z);
            po.w = fmaf(s1, st[1].w, s0 * st[0].w);

            float* ob = opart +
                ((size_t)((size_t)t * B_DIM + b) * G_GRP + g) * F_DIM + 4 * l;
            *(float4*)ob = po;
        }

        __syncwarp();
        if (cc + 2 < NCHUNK) ISSUE_CHUNK(cc + 2, bi);
    }
#undef ISSUE_CHUNK

    float* so = state_out + ((size_t)b * F_DIM + rowbase) * F_DIM + 4 * l;
#pragma unroll
    for (int r = 0; r < R_ROWS; r++)
        *(float4*)(so + r * F_DIM) = st[r];
}

// ---------------------------------------------------------------------------
// K3: reduce partial outputs over G, emitting bf16 hi/lo for K4
// ---------------------------------------------------------------------------
__global__ void reduce_opart_kernel(const float* __restrict__ opart)
{
    const int F4 = F_DIM / 4;
    size_t idx = (size_t)blockIdx.x * blockDim.x + threadIdx.x;
    size_t total = (size_t)M_DIM * F4;
    if (idx >= total) return;
    size_t row = idx / F4;
    int f4 = (int)(idx % F4);
    const float4* src = (const float4*)opart + row * (size_t)(G_GRP * F4) + f4;
    float4 acc = make_float4(0.f, 0.f, 0.f, 0.f);
#pragma unroll
    for (int gg = 0; gg < G_GRP; gg++) {
        float4 xv = src[(size_t)gg * F4];
        acc.x += xv.x; acc.y += xv.y; acc.z += xv.z; acc.w += xv.w;
    }
    __nv_bfloat16 h0, l0, h1, l1, h2, l2, h3, l3;
    split1(acc.x, h0, l0); split1(acc.y, h1, l1);
    split1(acc.z, h2, l2); split1(acc.w, h3, l3);
    uint2 ph, pl;
    ph.x = (uint32_t)__bfloat16_as_ushort(h0) | ((uint32_t)__bfloat16_as_ushort(h1) << 16);
    ph.y = (uint32_t)__bfloat16_as_ushort(h2) | ((uint32_t)__bfloat16_as_ushort(h3) << 16);
    pl.x = (uint32_t)__bfloat16_as_ushort(l0) | ((uint32_t)__bfloat16_as_ushort(l1) << 16);
    pl.y = (uint32_t)__bfloat16_as_ushort(l2) | ((uint32_t)__bfloat16_as_ushort(l3) << 16);
    ((uint2*)d_oh)[idx] = ph;
    ((uint2*)d_ol)[idx] = pl;
}

// ---------------------------------------------------------------------------
// launch
// ---------------------------------------------------------------------------
extern "C" void kernel_launch(void* const* d_in, const int* in_sizes, int n_in,
                              void* d_out, int out_size)
{
    const float* x     = (const float*)d_in[0];
    const float* state = (const float*)d_in[1];
    const float* A_w = (const float*)d_in[2];
    const float* A_b = (const float*)d_in[3];
    const float* B_w = (const float*)d_in[4];
    const float* B_b = (const float*)d_in[5];
    const float* C_w = (const float*)d_in[6];
    const float* C_b = (const float*)d_in[7];
    const float* D_w = (const float*)d_in[8];
    const float* D_b = (const float*)d_in[9];
    const float* I_w = (const float*)d_in[10];
    const float* I_b = (const float*)d_in[11];
    const float* S_w = (const float*)d_in[12];
    const float* S_b = (const float*)d_in[13];
    const float* O_w = (const float*)d_in[14];

    float* out = (float*)d_out;

    float *b6, *P, *opart, *stfb;
    __nv_bfloat16 *xh, *xl, *W6h, *W6l, *Owh, *Owl, *oh, *ol;
    cudaGetSymbolAddress((void**)&b6, d_b6);
    cudaGetSymbolAddress((void**)&P, d_P);
    cudaGetSymbolAddress((void**)&opart, d_opart);
    cudaGetSymbolAddress((void**)&stfb, d_stfb);
    cudaGetSymbolAddress((void**)&xh, d_xh);
    cudaGetSymbolAddress((void**)&xl, d_xl);
    cudaGetSymbolAddress((void**)&W6h, d_W6h);
    cudaGetSymbolAddress((void**)&W6l, d_W6l);
    cudaGetSymbolAddress((void**)&Owh, d_Owh);
    cudaGetSymbolAddress((void**)&Owl, d_Owl);
    cudaGetSymbolAddress((void**)&oh, d_oh);
    cudaGetSymbolAddress((void**)&ol, d_ol);

    cudaFuncSetAttribute(bf16_gemm_async,
                         cudaFuncAttributeMaxDynamicSharedMemorySize, GEMM_SMEM);
    cudaFuncSetAttribute(scan_kernel,
                         cudaFuncAttributeMaxDynamicSharedMemorySize, SCAN_SMEM);

    const size_t y_elems = (size_t)M_DIM * C_DIM;
    const size_t st_elems = (size_t)B_DIM * F_DIM * F_DIM;
    float* y = out;
    float* state_out =
        ((size_t)out_size >= y_elems + st_elems) ? (out + y_elems) : stfb;

    // pos 1: pack weights + split x (merged)
    {
        size_t total4 = (size_t)M_DIM * C_DIM / 4;
        pack_split_kernel<<<(unsigned)((total4 + 255) / 256), 256>>>(
            x, A_w, B_w, C_w, D_w, I_w, S_w,
            A_b, B_b, C_b, D_b, I_b, S_b, O_w);
    }

    // pos 2: K1  P = x @ W6^T + b6 (+ b-scale / i-sigmoid epilogue)
    {
        dim3 grid(N6 / 128, M_DIM / 128);
        bf16_gemm_async<<<grid, 256, GEMM_SMEM>>>(xh, xl, W6h, W6l, b6, P,
                                                  M_DIM, N6, C_DIM);
    }

    // pos 3: noop (keeps scan at ncu capture position 4)
    noop_kernel<<<1, 1>>>();

    // pos 4: scan (ncu capture position) — G=64, 2 rows per warp
    {
        dim3 grid(G_GRP, B_DIM);
        scan_kernel<<<grid, 32, SCAN_SMEM>>>(P, state, opart, state_out);
    }

    // pos 5: reduce partials -> bf16 hi/lo o
    {
        size_t total = (size_t)M_DIM * (F_DIM / 4);
        reduce_opart_kernel<<<(unsigned)((total + 255) / 256), 256>>>(opart);
    }

    // pos 6: K4  y = o @ O_w^T  (M=32768, N=1024, K=128)
    {
        dim3 grid(C_DIM / 128, M_DIM / 128);
        bf16_gemm_async<<<grid, 256, GEMM_SMEM>>>(oh, ol, Owh, Owl, nullptr, y,
                                                  M_DIM, C_DIM, F_DIM);
    }
}

// round 15
// speedup vs baseline: 1.4578x; 1.4578x over previous
#include <cuda_runtime.h>
#include <cuda_bf16.h>
#include <math.h>
#include <stdint.h>

// Problem dims
#define T_DIM 4096
#define B_DIM 8
#define C_DIM 1024
#define F_DIM 128
#define NPROJ 6
#define N6 (NPROJ * F_DIM)          // 768
#define M_DIM (T_DIM * B_DIM)       // 32768
#define G_GRP 64                    // row groups per batch for scan
#define R_ROWS (F_DIM / G_GRP)      // 2 rows per warp

#define INV_SQRT_F 0.08838834764831845f  // 1/sqrt(128)

// Scan SMEM pipeline
#define CHUNK 8                     // steps per chunk (33KB total -> 1 wave)
#define SLOT_F 528                  // floats per step slot (4*128 + c + s + pad)
#define BUF_F (CHUNK * SLOT_F)      // floats per chunk buffer
#define SCAN_SMEM (2 * BUF_F * 4)   // bytes (33792)

// ---------------------------------------------------------------------------
// Scratch (static device arrays: allocation-free per harness rules)
// ---------------------------------------------------------------------------
__device__ float d_b6[N6];                                            // packed biases
__device__ float d_P[(size_t)M_DIM * N6];                             // 96 MB projections
__device__ float d_opart[(size_t)M_DIM * G_GRP * F_DIM];              // 1 GB partials
__device__ float d_stfb[(size_t)B_DIM * F_DIM * F_DIM];               // state fallback
__device__ __nv_bfloat16 d_xh[(size_t)M_DIM * C_DIM];                 // 64 MB x hi
__device__ __nv_bfloat16 d_xl[(size_t)M_DIM * C_DIM];                 // 64 MB x lo
__device__ __nv_bfloat16 d_W6h[(size_t)N6 * C_DIM];                   // 1.5 MB
__device__ __nv_bfloat16 d_W6l[(size_t)N6 * C_DIM];                   // 1.5 MB
__device__ __nv_bfloat16 d_Owh[(size_t)C_DIM * F_DIM];
__device__ __nv_bfloat16 d_Owl[(size_t)C_DIM * F_DIM];
__device__ __nv_bfloat16 d_oh[(size_t)M_DIM * F_DIM];                 // 8 MB
__device__ __nv_bfloat16 d_ol[(size_t)M_DIM * F_DIM];                 // 8 MB

// ---------------------------------------------------------------------------
// helpers
// ---------------------------------------------------------------------------
__device__ __forceinline__ void split1(float v, __nv_bfloat16& h, __nv_bfloat16& l) {
    h = __float2bfloat16_rn(v);
    l = __float2bfloat16_rn(v - __bfloat162float(h));
}

__device__ __forceinline__ void cp16(uint32_t dst, const void* src) {
    asm volatile("cp.async.ca.shared.global [%0], [%1], 16;"
                 :: "r"(dst), "l"(src));
}

__device__ __forceinline__ void cp8(uint32_t dst, const void* src) {
    asm volatile("cp.async.ca.shared.global [%0], [%1], 8;"
                 :: "r"(dst), "l"(src));
}

// dummy kernel: keeps the scan at ncu capture position 4
__global__ void noop_kernel() {}

// ---------------------------------------------------------------------------
// K0: pack biases + split weights AND x into bf16 hi/lo (merged kernel)
// ---------------------------------------------------------------------------
__global__ void pack_split_kernel(
    const float* __restrict__ xin,
    const float* __restrict__ Aw, const float* __restrict__ Bw,
    const float* __restrict__ Cw, const float* __restrict__ Dw,
    const float* __restrict__ Iw, const float* __restrict__ Sw,
    const float* __restrict__ Ab, const float* __restrict__ Bb,
    const float* __restrict__ Cb, const float* __restrict__ Db,
    const float* __restrict__ Ib, const float* __restrict__ Sb,
    const float* __restrict__ Ow)
{
    size_t i4 = (size_t)blockIdx.x * blockDim.x + threadIdx.x;
    const size_t total4 = (size_t)M_DIM * C_DIM / 4;
    if (i4 < total4) {
        float4 v = ((const float4*)xin)[i4];
        __nv_bfloat16 h0, l0, h1, l1, h2, l2, h3, l3;
        split1(v.x, h0, l0); split1(v.y, h1, l1);
        split1(v.z, h2, l2); split1(v.w, h3, l3);
        uint2 ph, pl;
        ph.x = (uint32_t)__bfloat16_as_ushort(h0) | ((uint32_t)__bfloat16_as_ushort(h1) << 16);
        ph.y = (uint32_t)__bfloat16_as_ushort(h2) | ((uint32_t)__bfloat16_as_ushort(h3) << 16);
        pl.x = (uint32_t)__bfloat16_as_ushort(l0) | ((uint32_t)__bfloat16_as_ushort(l1) << 16);
        pl.y = (uint32_t)__bfloat16_as_ushort(l2) | ((uint32_t)__bfloat16_as_ushort(l3) << 16);
        ((uint2*)d_xh)[i4] = ph;
        ((uint2*)d_xl)[i4] = pl;
    }
    const size_t per = (size_t)F_DIM * C_DIM;  // 131072
    if (i4 < per) {
        size_t i = i4;
        split1(Aw[i], d_W6h[0 * per + i], d_W6l[0 * per + i]);
        split1(Bw[i], d_W6h[1 * per + i], d_W6l[1 * per + i]);
        split1(Cw[i], d_W6h[2 * per + i], d_W6l[2 * per + i]);
        split1(Dw[i], d_W6h[3 * per + i], d_W6l[3 * per + i]);
        split1(Iw[i], d_W6h[4 * per + i], d_W6l[4 * per + i]);
        split1(Sw[i], d_W6h[5 * per + i], d_W6l[5 * per + i]);
        split1(Ow[i], d_Owh[i], d_Owl[i]);
    }
    if (i4 < F_DIM) {
        size_t i = i4;
        d_b6[0 * F_DIM + i] = Ab[i];
        d_b6[1 * F_DIM + i] = Bb[i];
        d_b6[2 * F_DIM + i] = Cb[i];
        d_b6[3 * F_DIM + i] = Db[i];
        d_b6[4 * F_DIM + i] = Ib[i];
        d_b6[5 * F_DIM + i] = Sb[i];
    }
}

// ---------------------------------------------------------------------------
// K1/K4: 3xBF16 GEMM, cp.async 2-stage pipeline + ldmatrix + mma.m16n8k16 (NT)
// Epilogue transform (K1 only, bias != null, N == N6): N-tile 1 (slot b)
// multiplies by 1/sqrt(F); N-tile 4 (slot i) applies sigmoid.
// ---------------------------------------------------------------------------
#define ASTRIDE 40
#define TILE_E (128 * ASTRIDE)
#define TILE_B (TILE_E * 2)
#define STAGE_B (4 * TILE_B)
#define GEMM_SMEM (2 * STAGE_B)

__device__ __forceinline__ void ldm_x4(uint32_t (&r)[4], const __nv_bfloat16* p) {
    uint32_t addr = (uint32_t)__cvta_generic_to_shared(p);
    asm volatile("ldmatrix.sync.aligned.m8n8.x4.shared.b16 {%0,%1,%2,%3}, [%4];"
                 : "=r"(r[0]), "=r"(r[1]), "=r"(r[2]), "=r"(r[3]) : "r"(addr));
}

__device__ __forceinline__ void mma_bf16(float* d, const uint32_t* a,
                                         uint32_t b0, uint32_t b1) {
    asm volatile(
        "mma.sync.aligned.m16n8k16.row.col.f32.bf16.bf16.f32 "
        "{%0,%1,%2,%3}, {%4,%5,%6,%7}, {%8,%9}, {%0,%1,%2,%3};"
        : "+f"(d[0]), "+f"(d[1]), "+f"(d[2]), "+f"(d[3])
        : "r"(a[0]), "r"(a[1]), "r"(a[2]), "r"(a[3]), "r"(b0), "r"(b1));
}

__device__ __forceinline__ float epi_op(float v, int mode) {
    if (mode == 1) return v * INV_SQRT_F;
    if (mode == 2) return 1.0f / (1.0f + __expf(-v));
    return v;
}

__global__ void __launch_bounds__(256, 2)
bf16_gemm_async(const __nv_bfloat16* __restrict__ Ah,
                const __nv_bfloat16* __restrict__ Al,
                const __nv_bfloat16* __restrict__ Bh,
                const __nv_bfloat16* __restrict__ Bl,
                const float* __restrict__ bias, float* __restrict__ C,
                int M, int N, int K)
{
    extern __shared__ __align__(16) __nv_bfloat16 smd[];

    const int tid = threadIdx.x;
    const int wid = tid >> 5;
    const int lane = tid & 31;
    const int grp = lane >> 2;
    const int tig = lane & 3;

    const int bm = blockIdx.y * 128;
    const int bn = blockIdx.x * 128;
    const int warp_m = (wid >> 1) * 32;
    const int warp_n = (wid & 1) * 64;

    float acc[2][8][4];
#pragma unroll
    for (int mt = 0; mt < 2; mt++)
#pragma unroll
        for (int nt = 0; nt < 8; nt++)
#pragma unroll
            for (int q = 0; q < 4; q++) acc[mt][nt][q] = 0.0f;

    const int lrow = tid >> 1;
    const int cb = (tid & 1) * 2;

    const __nv_bfloat16* gsrc[4];
    gsrc[0] = Ah + (size_t)(bm + lrow) * K;
    gsrc[1] = Al + (size_t)(bm + lrow) * K;
    gsrc[2] = Bh + (size_t)(bn + lrow) * K;
    gsrc[3] = Bl + (size_t)(bn + lrow) * K;

    const uint32_t smem_base = (uint32_t)__cvta_generic_to_shared(smd);
    const uint32_t dst0 = smem_base + (uint32_t)(lrow * ASTRIDE * 2 + cb * 16);

    const int a_e0 = (warp_m + (lane & 15)) * ASTRIDE + ((lane >> 4) & 1) * 8;
    const int b_e0 = (warp_n + (lane & 7) + ((lane >> 4) & 1) * 8) * ASTRIDE
                   + ((lane >> 3) & 1) * 8;

#define ISSUE_STAGE(stg, kk) do {                                          \
    uint32_t _d = dst0 + (uint32_t)(stg) * STAGE_B;                        \
    _Pragma("unroll")                                                      \
    for (int _m = 0; _m < 4; _m++) {                                       \
        cp16(_d + 0,  gsrc[_m] + (kk) + (cb + 0) * 8);                     \
        cp16(_d + 16, gsrc[_m] + (kk) + (cb + 1) * 8);                     \
        _d += TILE_B;                                                      \
    }                                                                      \
    asm volatile("cp.async.commit_group;");                                \
} while (0)

    const int niter = K >> 5;
    ISSUE_STAGE(0, 0);

    for (int i = 0; i < niter; i++) {
        if (i + 1 < niter) {
            ISSUE_STAGE((i + 1) & 1, (i + 1) * 32);
            asm volatile("cp.async.wait_group 1;");
        } else {
            asm volatile("cp.async.wait_group 0;");
        }
        __syncthreads();

        const __nv_bfloat16* sAh = smd + (size_t)((i & 1) * 4 + 0) * TILE_E;
        const __nv_bfloat16* sAl = smd + (size_t)((i & 1) * 4 + 1) * TILE_E;
        const __nv_bfloat16* sBh = smd + (size_t)((i & 1) * 4 + 2) * TILE_E;
        const __nv_bfloat16* sBl = smd + (size_t)((i & 1) * 4 + 3) * TILE_E;

#pragma unroll
        for (int ks = 0; ks < 2; ks++) {
            uint32_t afh[2][4], afl[2][4];
#pragma unroll
            for (int mt = 0; mt < 2; mt++) {
                int e = a_e0 + mt * 16 * ASTRIDE + ks * 16;
                ldm_x4(afh[mt], sAh + e);
                ldm_x4(afl[mt], sAl + e);
            }
#pragma unroll
            for (int ntp = 0; ntp < 4; ntp++) {
                uint32_t bh[4], bl[4];
                int e = b_e0 + ntp * 16 * ASTRIDE + ks * 16;
                ldm_x4(bh, sBh + e);
                ldm_x4(bl, sBl + e);
#pragma unroll
                for (int mt = 0; mt < 2; mt++) {
                    mma_bf16(acc[mt][2 * ntp],     afh[mt], bh[0], bh[1]);
                    mma_bf16(acc[mt][2 * ntp],     afh[mt], bl[0], bl[1]);
                    mma_bf16(acc[mt][2 * ntp],     afl[mt], bh[0], bh[1]);
                    mma_bf16(acc[mt][2 * ntp + 1], afh[mt], bh[2], bh[3]);
                    mma_bf16(acc[mt][2 * ntp + 1], afh[mt], bl[2], bl[3]);
                    mma_bf16(acc[mt][2 * ntp + 1], afl[mt], bh[2], bh[3]);
                }
            }
        }
        __syncthreads();
    }
#undef ISSUE_STAGE

    int mode = 0;
    if (bias != nullptr && N == N6) {
        if (bn == 1 * F_DIM) mode = 1;        // slot b: scale by 1/sqrt(F)
        else if (bn == 4 * F_DIM) mode = 2;   // slot i: sigmoid
    }

#pragma unroll
    for (int mt = 0; mt < 2; mt++) {
        int r0 = bm + warp_m + mt * 16 + grp;
#pragma unroll
        for (int nt = 0; nt < 8; nt++) {
            int col = bn + warp_n + nt * 8 + 2 * tig;
            float b0 = 0.f, b1 = 0.f;
            if (bias != nullptr) { b0 = bias[col]; b1 = bias[col + 1]; }
            float2 v0 = make_float2(epi_op(acc[mt][nt][0] + b0, mode),
                                    epi_op(acc[mt][nt][1] + b1, mode));
            float2 v1 = make_float2(epi_op(acc[mt][nt][2] + b0, mode),
                                    epi_op(acc[mt][nt][3] + b1, mode));
            *(float2*)(C + (size_t)r0 * N + col) = v0;
            *(float2*)(C + (size_t)(r0 + 8) * N + col) = v1;
        }
    }
}

// ---------------------------------------------------------------------------
// K2: sequential scan with SMEM chunk pipeline. G_GRP=64 -> 2 rows per warp.
// CHUNK=8 keeps SMEM at 33KB so all 512 CTAs run in ONE wave.
// Grid (G_GRP, B_DIM), 32 threads per CTA. Lane l owns columns [4l, 4l+4).
// Slot b pre-scaled, slot i pre-sigmoided (GEMM epilogue).
// c/s copied with 8-byte cp.async (global offset 8g only 8B-aligned).
// 2-way warp reduction: 7 shfls.
// Slot layout (floats): a[0..127], b'[128..255], d[256..383], g[384..511],
//                       c[512..513], s[516..517], pad -> SLOT_F
// ---------------------------------------------------------------------------
__global__ void __launch_bounds__(32)
scan_kernel(const float* __restrict__ P, const float* __restrict__ state_in,
            float* __restrict__ opart, float* __restrict__ state_out)
{
    extern __shared__ __align__(16) float sm[];

    const int g = blockIdx.x;
    const int b = blockIdx.y;
    const int l = threadIdx.x;
    const int rowbase = g * R_ROWS;

    const uint32_t smb = (uint32_t)__cvta_generic_to_shared(sm);

#define ISSUE_CHUNK(cc, bi) do {                                              \
    const int _t0 = (cc) * CHUNK;                                             \
    _Pragma("unroll 4")                                                       \
    for (int _s = 0; _s < CHUNK; _s++) {                                      \
        const float* _src = P + (size_t)((size_t)(_t0 + _s) * B_DIM + b) * N6;\
        uint32_t _dst = smb + (uint32_t)(((bi) * BUF_F + _s * SLOT_F) * 4);   \
        cp16(_dst + (uint32_t)(l * 16),          _src + 0 * F_DIM + l * 4);   \
        cp16(_dst + (uint32_t)(512 + l * 16),    _src + 1 * F_DIM + l * 4);   \
        cp16(_dst + (uint32_t)(1024 + l * 16),   _src + 3 * F_DIM + l * 4);   \
        cp16(_dst + (uint32_t)(1536 + l * 16),   _src + 4 * F_DIM + l * 4);   \
        if (l == 0) cp8(_dst + 2048, _src + 2 * F_DIM + rowbase);             \
        if (l == 1) cp8(_dst + 2064, _src + 5 * F_DIM + rowbase);             \
    }                                                                         \
    asm volatile("cp.async.commit_group;");                                   \
} while (0)

    // initial state
    float4 st[R_ROWS];
    {
        const float* sb = state_in + ((size_t)b * F_DIM + rowbase) * F_DIM + 4 * l;
#pragma unroll
        for (int r = 0; r < R_ROWS; r++)
            st[r] = *(const float4*)(sb + r * F_DIM);
    }

    ISSUE_CHUNK(0, 0);
    ISSUE_CHUNK(1, 1);

    const bool hi16 = (l & 16) != 0;

    const int NCHUNK = T_DIM / CHUNK;   // 512
#pragma unroll 1
    for (int cc = 0; cc < NCHUNK; cc++) {
        asm volatile("cp.async.wait_group 1;");
        __syncwarp();

        const int bi = cc & 1;
        const float* buf = sm + (size_t)bi * BUF_F;

#pragma unroll 4
        for (int s = 0; s < CHUNK; s++) {
            const int t = cc * CHUNK + s;
            const float* sp = buf + s * SLOT_F;

            float4 a  = *(const float4*)(sp + 4 * l);
            float4 bb = *(const float4*)(sp + 128 + 4 * l);   // pre-scaled
            float4 dd = *(const float4*)(sp + 256 + 4 * l);
            float4 gg = *(const float4*)(sp + 384 + 4 * l);   // pre-sigmoided

            // per-lane partial dots (2 rows)
            float p0, p1;
            {
                float m01 = fmaf(st[0].y, a.y, st[0].x * a.x);
                float m23 = fmaf(st[0].w, a.w, st[0].z * a.z);
                p0 = m01 + m23;
                float n01 = fmaf(st[1].y, a.y, st[1].x * a.x);
                float n23 = fmaf(st[1].w, a.w, st[1].z * a.z);
                p1 = n01 + n23;
            }

            // 7-shfl 2-way allsum:
            float sA = hi16 ? p0 : p1;
            float rA = __shfl_xor_sync(0xffffffffu, sA, 16);
            float w = (hi16 ? p1 : p0) + rA;   // lo half: row0, hi half: row1
            w += __shfl_xor_sync(0xffffffffu, w, 8);
            w += __shfl_xor_sync(0xffffffffu, w, 4);
            w += __shfl_xor_sync(0xffffffffu, w, 2);
            w += __shfl_xor_sync(0xffffffffu, w, 1);
            float v0 = __shfl_sync(0xffffffffu, w, 0);
            float v1 = __shfl_sync(0xffffffffu, w, 16);

            const float c0 = sp[512];
            const float c1 = sp[513];
            const float s0 = sp[516];
            const float s1 = sp[517];

            // st = st*g + v*b' + c*d ; po = s0*st0 + s1*st1
            st[0].x = fmaf(st[0].x, gg.x, fmaf(v0, bb.x, c0 * dd.x));
            st[0].y = fmaf(st[0].y, gg.y, fmaf(v0, bb.y, c0 * dd.y));
            st[0].z = fmaf(st[0].z, gg.z, fmaf(v0, bb.z, c0 * dd.z));
            st[0].w = fmaf(st[0].w, gg.w, fmaf(v0, bb.w, c0 * dd.w));
            st[1].x = fmaf(st[1].x, gg.x, fmaf(v1, bb.x, c1 * dd.x));
            st[1].y = fmaf(st[1].y, gg.y, fmaf(v1, bb.y, c1 * dd.y));
            st[1].z = fmaf(st[1].z, gg.z, fmaf(v1, bb.z, c1 * dd.z));
            st[1].w = fmaf(st[1].w, gg.w, fmaf(v1, bb.w, c1 * dd.w));

            float4 po;
            po.x = fmaf(s1, st[1].x, s0 * st[0].x);
            po.y = fmaf(s1, st[1].y, s0 * st[0].y);
            po.z = fmaf(s1, st[1].z, s0 * st[0].z);
            po.w = fmaf(s1, st[1].w, s0 * st[0].w);

            float* ob = opart +
                ((size_t)((size_t)t * B_DIM + b) * G_GRP + g) * F_DIM + 4 * l;
            *(float4*)ob = po;
        }

        __syncwarp();
        if (cc + 2 < NCHUNK) ISSUE_CHUNK(cc + 2, bi);
    }
#undef ISSUE_CHUNK

    float* so = state_out + ((size_t)b * F_DIM + rowbase) * F_DIM + 4 * l;
#pragma unroll
    for (int r = 0; r < R_ROWS; r++)
        *(float4*)(so + r * F_DIM) = st[r];
}

// ---------------------------------------------------------------------------
// K3: reduce partial outputs over G, emitting bf16 hi/lo for K4
// ---------------------------------------------------------------------------
__global__ void reduce_opart_kernel(const float* __restrict__ opart)
{
    const int F4 = F_DIM / 4;
    size_t idx = (size_t)blockIdx.x * blockDim.x + threadIdx.x;
    size_t total = (size_t)M_DIM * F4;
    if (idx >= total) return;
    size_t row = idx / F4;
    int f4 = (int)(idx % F4);
    const float4* src = (const float4*)opart + row * (size_t)(G_GRP * F4) + f4;
    float4 acc = make_float4(0.f, 0.f, 0.f, 0.f);
#pragma unroll
    for (int gg = 0; gg < G_GRP; gg++) {
        float4 xv = src[(size_t)gg * F4];
        acc.x += xv.x; acc.y += xv.y; acc.z += xv.z; acc.w += xv.w;
    }
    __nv_bfloat16 h0, l0, h1, l1, h2, l2, h3, l3;
    split1(acc.x, h0, l0); split1(acc.y, h1, l1);
    split1(acc.z, h2, l2); split1(acc.w, h3, l3);
    uint2 ph, pl;
    ph.x = (uint32_t)__bfloat16_as_ushort(h0) | ((uint32_t)__bfloat16_as_ushort(h1) << 16);
    ph.y = (uint32_t)__bfloat16_as_ushort(h2) | ((uint32_t)__bfloat16_as_ushort(h3) << 16);
    pl.x = (uint32_t)__bfloat16_as_ushort(l0) | ((uint32_t)__bfloat16_as_ushort(l1) << 16);
    pl.y = (uint32_t)__bfloat16_as_ushort(l2) | ((uint32_t)__bfloat16_as_ushort(l3) << 16);
    ((uint2*)d_oh)[idx] = ph;
    ((uint2*)d_ol)[idx] = pl;
}

// ---------------------------------------------------------------------------
// launch
// ---------------------------------------------------------------------------
extern "C" void kernel_launch(void* const* d_in, const int* in_sizes, int n_in,
                              void* d_out, int out_size)
{
    const float* x     = (const float*)d_in[0];
    const float* state = (const float*)d_in[1];
    const float* A_w = (const float*)d_in[2];
    const float* A_b = (const float*)d_in[3];
    const float* B_w = (const float*)d_in[4];
    const float* B_b = (const float*)d_in[5];
    const float* C_w = (const float*)d_in[6];
    const float* C_b = (const float*)d_in[7];
    const float* D_w = (const float*)d_in[8];
    const float* D_b = (const float*)d_in[9];
    const float* I_w = (const float*)d_in[10];
    const float* I_b = (const float*)d_in[11];
    const float* S_w = (const float*)d_in[12];
    const float* S_b = (const float*)d_in[13];
    const float* O_w = (const float*)d_in[14];

    float* out = (float*)d_out;

    float *b6, *P, *opart, *stfb;
    __nv_bfloat16 *xh, *xl, *W6h, *W6l, *Owh, *Owl, *oh, *ol;
    cudaGetSymbolAddress((void**)&b6, d_b6);
    cudaGetSymbolAddress((void**)&P, d_P);
    cudaGetSymbolAddress((void**)&opart, d_opart);
    cudaGetSymbolAddress((void**)&stfb, d_stfb);
    cudaGetSymbolAddress((void**)&xh, d_xh);
    cudaGetSymbolAddress((void**)&xl, d_xl);
    cudaGetSymbolAddress((void**)&W6h, d_W6h);
    cudaGetSymbolAddress((void**)&W6l, d_W6l);
    cudaGetSymbolAddress((void**)&Owh, d_Owh);
    cudaGetSymbolAddress((void**)&Owl, d_Owl);
    cudaGetSymbolAddress((void**)&oh, d_oh);
    cudaGetSymbolAddress((void**)&ol, d_ol);

    cudaFuncSetAttribute(bf16_gemm_async,
                         cudaFuncAttributeMaxDynamicSharedMemorySize, GEMM_SMEM);
    cudaFuncSetAttribute(scan_kernel,
                         cudaFuncAttributeMaxDynamicSharedMemorySize, SCAN_SMEM);

    const size_t y_elems = (size_t)M_DIM * C_DIM;
    const size_t st_elems = (size_t)B_DIM * F_DIM * F_DIM;
    float* y = out;
    float* state_out =
        ((size_t)out_size >= y_elems + st_elems) ? (out + y_elems) : stfb;

    // pos 1: pack weights + split x (merged)
    {
        size_t total4 = (size_t)M_DIM * C_DIM / 4;
        pack_split_kernel<<<(unsigned)((total4 + 255) / 256), 256>>>(
            x, A_w, B_w, C_w, D_w, I_w, S_w,
            A_b, B_b, C_b, D_b, I_b, S_b, O_w);
    }

    // pos 2: K1  P = x @ W6^T + b6 (+ b-scale / i-sigmoid epilogue)
    {
        dim3 grid(N6 / 128, M_DIM / 128);
        bf16_gemm_async<<<grid, 256, GEMM_SMEM>>>(xh, xl, W6h, W6l, b6, P,
                                                  M_DIM, N6, C_DIM);
    }

    // pos 3: noop (keeps scan at ncu capture position 4)
    noop_kernel<<<1, 1>>>();

    // pos 4: scan (ncu capture position) — G=64, 2 rows per warp, 1 wave
    {
        dim3 grid(G_GRP, B_DIM);
        scan_kernel<<<grid, 32, SCAN_SMEM>>>(P, state, opart, state_out);
    }

    // pos 5: reduce partials -> bf16 hi/lo o
    {
        size_t total = (size_t)M_DIM * (F_DIM / 4);
        reduce_opart_kernel<<<(unsigned)((total + 255) / 256), 256>>>(opart);
    }

    // pos 6: K4  y = o @ O_w^T  (M=32768, N=1024, K=128)
    {
        dim3 grid(C_DIM / 128, M_DIM / 128);
        bf16_gemm_async<<<grid, 256, GEMM_SMEM>>>(oh, ol, Owh, Owl, nullptr, y,
                                                  M_DIM, C_DIM, F_DIM);
    }
}